// round 1
// baseline (speedup 1.0000x reference)
#include <cuda_runtime.h>
#include <cstdint>

// Problem constants (FrustumPooling_721554506291)
#define Bb 2
#define Nn 4
#define Dd 48
#define Hh 28
#define Ww 60
#define Cc 64
#define NX 192
#define NY 192
// NZ = 1
#define TT (Bb*Dd*Hh*Ww)          // 161280 point-tasks (n folded inside)
#define SCRATCH_ELEMS (Bb*NY*NX*Cc)  // 4,718,592 floats (~18.9 MB)

// Scratch accumulator in [b][y][x][c] layout (channels contiguous -> v4 atomics)
__device__ float g_scratch[SCRATCH_ELEMS];
// Per-(b,n): combine[9] followed by trans[3]
__device__ float g_combine[Bb*Nn*12];

// ---------------------------------------------------------------------------
// Setup: combine = rots @ inv(K), trans = pose[:3,3]   (8 threads total)
// ---------------------------------------------------------------------------
__global__ void setup_kernel(const float* __restrict__ intr,
                             const float* __restrict__ pose)
{
    int i = threadIdx.x;
    if (i >= Bb*Nn) return;
    const float* K = intr + i*9;
    const float* P = pose + i*16;

    float a=K[0], b=K[1], c=K[2];
    float d=K[3], e=K[4], f=K[5];
    float g=K[6], h=K[7], ii=K[8];
    float A0 =  (e*ii - f*h);
    float A1 = -(d*ii - f*g);
    float A2 =  (d*h  - e*g);
    float det = a*A0 + b*A1 + c*A2;
    float id  = 1.0f / det;
    float inv[9];
    inv[0] = A0*id;           inv[1] = (c*h - b*ii)*id; inv[2] = (b*f - c*e)*id;
    inv[3] = A1*id;           inv[4] = (a*ii - c*g)*id; inv[5] = (c*d - a*f)*id;
    inv[6] = A2*id;           inv[7] = (b*g - a*h)*id;  inv[8] = (a*e - b*d)*id;

    float* out = g_combine + i*12;
    #pragma unroll
    for (int r = 0; r < 3; r++) {
        #pragma unroll
        for (int col = 0; col < 3; col++) {
            out[r*3+col] = P[r*4+0]*inv[0*3+col]
                         + P[r*4+1]*inv[1*3+col]
                         + P[r*4+2]*inv[2*3+col];
        }
        out[9+r] = P[r*4+3];
    }
}

// ---------------------------------------------------------------------------
// Zero the scratch accumulator (float4 stores)
// ---------------------------------------------------------------------------
__global__ void zero_kernel()
{
    int i = blockIdx.x * blockDim.x + threadIdx.x;   // one float4 each
    float4* p = reinterpret_cast<float4*>(g_scratch);
    if (i < SCRATCH_ELEMS/4)
        p[i] = make_float4(0.f, 0.f, 0.f, 0.f);
}

__device__ __forceinline__ void red4(float* addr, float4 v)
{
    asm volatile("red.global.add.v4.f32 [%0], {%1,%2,%3,%4};"
                 :: "l"(addr), "f"(v.x), "f"(v.y), "f"(v.z), "f"(v.w)
                 : "memory");
}

__device__ __forceinline__ void acc4(float4& a, const float4& b)
{
    a.x += b.x; a.y += b.y; a.z += b.z; a.w += b.w;
}

// ---------------------------------------------------------------------------
// Scatter: each 16-thread group handles one (b,d,h,w) point over all n.
// Each thread owns 4 channels (float4). Equal cell indices across n are
// merged in registers before issuing red.global.add.v4.f32.
// ---------------------------------------------------------------------------
__global__ void __launch_bounds__(256)
scatter_kernel(const float* __restrict__ x)
{
    int t    = blockIdx.x * 16 + (threadIdx.x >> 4);
    int lane = threadIdx.x & 15;
    if (t >= TT) return;

    int w = t % Ww;  int tmp = t / Ww;
    int h = tmp % Hh; tmp /= Hh;
    int d = tmp % Dd;
    int b = tmp / Dd;

    // frustum coords (match jnp.linspace / arange semantics in f32)
    float u  = (float)w * (479.0f/59.0f);
    float v  = (float)h * (223.0f/27.0f);
    float df = 2.0f + (float)d;
    float ud = u * df;
    float vd = v * df;

    // register-merged accumulation groups (fully unrolled, distinct sentinels)
    int    i0 = -1, i1 = -2, i2 = -3, i3 = -4;
    float4 v0, v1, v2, v3;

    #pragma unroll
    for (int n = 0; n < Nn; n++) {
        const float* cm = g_combine + (b*Nn + n)*12;
        float g0 = cm[0]*ud + cm[1]*vd + cm[2]*df; g0 += cm[9];
        float g1 = cm[3]*ud + cm[4]*vd + cm[5]*df; g1 += cm[10];
        float g2 = cm[6]*ud + cm[7]*vd + cm[8]*df; g2 += cm[11];

        int gx = (int)(g0 * 4.0f + 96.0f);   // truncation toward zero, like astype(int32)
        int gy = (int)(g1 * 4.0f + 96.0f);
        int gz = (int)((g2 + 10.0f) / 20.0f);

        bool kept = (gx >= 0) && (gx < NX) && (gy >= 0) && (gy < NY)
                 && (gz >= 0) && (gz < 1);
        if (kept) {
            int cell = ((b*NY + gy)*NX + gx)*Cc + lane*4;
            const float4* src = reinterpret_cast<const float4*>(
                x + (size_t)((((b*Nn + n)*Dd + d)*Hh + h)*Ww + w)*Cc) + lane;
            float4 val = *src;
            if      (cell == i0) acc4(v0, val);
            else if (cell == i1) acc4(v1, val);
            else if (cell == i2) acc4(v2, val);
            else if (i0 < 0)     { i0 = cell; v0 = val; }
            else if (i1 < 0)     { i1 = cell; v1 = val; }
            else if (i2 < 0)     { i2 = cell; v2 = val; }
            else                 { i3 = cell; v3 = val; }
        }
    }

    if (i0 >= 0) red4(g_scratch + i0, v0);
    if (i1 >= 0) red4(g_scratch + i1, v1);
    if (i2 >= 0) red4(g_scratch + i2, v2);
    if (i3 >= 0) red4(g_scratch + i3, v3);
}

// ---------------------------------------------------------------------------
// Transpose scratch [b][y][x][c] -> out [b][c][y][x], smem 32x32 tiles
// grid = Bb * NY * (NX/32) * (Cc/32) = 2*192*6*2 = 4608 blocks, block (32,8)
// ---------------------------------------------------------------------------
__global__ void __launch_bounds__(256)
transpose_kernel(float* __restrict__ out)
{
    __shared__ float s[32][33];
    int blk = blockIdx.x;
    int tc  = blk % 2;          blk /= 2;     // c tile (0..1)
    int txt = blk % 6;          blk /= 6;     // x tile (0..5)
    int y   = blk % NY;         blk /= NY;
    int b   = blk;                            // 0..1

    int tx = threadIdx.x;   // 0..31
    int ty = threadIdx.y;   // 0..7

    int c = tc*32 + tx;
    #pragma unroll
    for (int k = 0; k < 4; k++) {
        int xc = txt*32 + ty*4 + k;
        s[ty*4 + k][tx] = g_scratch[((b*NY + y)*NX + xc)*Cc + c];
    }
    __syncthreads();
    int xo = txt*32 + tx;
    #pragma unroll
    for (int k = 0; k < 4; k++) {
        int co = tc*32 + ty*4 + k;
        out[(((size_t)b*Cc + co)*NY + y)*NX + xo] = s[tx][ty*4 + k];
    }
}

// ---------------------------------------------------------------------------
extern "C" void kernel_launch(void* const* d_in, const int* in_sizes, int n_in,
                              void* d_out, int out_size)
{
    const float* x    = (const float*)d_in[0];
    const float* intr = (const float*)d_in[1];
    const float* pose = (const float*)d_in[2];
    float* out = (float*)d_out;

    setup_kernel<<<1, 32>>>(intr, pose);
    zero_kernel<<<(SCRATCH_ELEMS/4 + 255)/256, 256>>>();
    scatter_kernel<<<(TT + 15)/16, 256>>>(x);
    transpose_kernel<<<Bb * NY * (NX/32) * (Cc/32), dim3(32, 8)>>>(out);
}